// round 2
// baseline (speedup 1.0000x reference)
#include <cuda_runtime.h>
#include <math.h>

// Problem constants: inputs [128, 3, 256, 256] fp32, H == W == 256 so one basis.
#define NDIM 256
#define NIMG 384                       // 128 * 3
#define TOTELEM (NIMG * NDIM * NDIM)   // 25,165,824 floats (~100.7 MB)
#define EPS 1e-13f

// Scratch + basis in static device memory (no runtime allocation allowed).
__device__ float g_scratch[TOTELEM];
__device__ float g_basis[NDIM * NDIM];   // C[k][i]  (row = frequency k)
__device__ float g_basisT[NDIM * NDIM];  // C^T[i][k]

// ---------------------------------------------------------------------------
// Basis generation: orthonormal DCT-II, computed in double for accuracy.
// 65536 elements — negligible cost per replay.
// ---------------------------------------------------------------------------
__global__ void gen_basis_kernel() {
    int idx = blockIdx.x * blockDim.x + threadIdx.x;
    if (idx >= NDIM * NDIM) return;
    int k = idx >> 8;       // / 256
    int i = idx & 255;      // % 256
    double s = (k == 0) ? sqrt(1.0 / NDIM) : sqrt(2.0 / NDIM);
    double v = s * cos(M_PI * (2.0 * i + 1.0) * (double)k / (2.0 * NDIM));
    g_basis[k * NDIM + i]  = (float)v;
    g_basisT[i * NDIM + k] = (float)v;
}

// ---------------------------------------------------------------------------
// Pass 1: Y[m, k2] = sum_j X[m, j] * C[k2, j]  == X @ C^T
//   M = 98304 (B*C*H rows), N = 256, K = 256.
// Tiling: block = 128x128 output, BK = 16, 256 threads, 8x8 per thread.
// ---------------------------------------------------------------------------
__global__ void __launch_bounds__(256) dct_pass1_kernel(const float* __restrict__ X) {
    __shared__ float As[16][128];   // A staged TRANSPOSED: As[k][m]
    __shared__ float Bs[16][128];   // Bs[k][n]

    const int tid = threadIdx.x;
    const int tx = tid & 15;        // column group
    const int ty = tid >> 4;        // row group
    const int m0 = blockIdx.x * 128;
    const int n0 = blockIdx.y * 128;

    float acc[8][8];
    #pragma unroll
    for (int i = 0; i < 8; i++)
        #pragma unroll
        for (int j = 0; j < 8; j++) acc[i][j] = 0.0f;

    for (int kt = 0; kt < NDIM; kt += 16) {
        // Load A tile (128 rows x 16 k) with float4, store transposed.
        #pragma unroll
        for (int r = 0; r < 2; r++) {
            int idx = tid + r * 256;
            int row = idx >> 2;          // 0..127
            int q   = idx & 3;           // which float4 within the 16-wide k chunk
            float4 v = *(const float4*)(X + (size_t)(m0 + row) * NDIM + kt + q * 4);
            As[q * 4 + 0][row] = v.x;
            As[q * 4 + 1][row] = v.y;
            As[q * 4 + 2][row] = v.z;
            As[q * 4 + 3][row] = v.w;
        }
        // Load B tile (16 k x 128 n) with float4.
        #pragma unroll
        for (int r = 0; r < 2; r++) {
            int idx = tid + r * 256;
            int k  = idx >> 5;           // 0..15
            int n4 = idx & 31;           // 0..31 float4 slots
            *(float4*)(&Bs[k][n4 * 4]) =
                *(const float4*)(g_basisT + (size_t)(kt + k) * NDIM + n0 + n4 * 4);
        }
        __syncthreads();

        #pragma unroll
        for (int k = 0; k < 16; k++) {
            float a[8], b[8];
            #pragma unroll
            for (int ii = 0; ii < 8; ii++) a[ii] = As[k][ty + 16 * ii];
            #pragma unroll
            for (int jj = 0; jj < 8; jj++) b[jj] = Bs[k][tx + 16 * jj];
            #pragma unroll
            for (int ii = 0; ii < 8; ii++)
                #pragma unroll
                for (int jj = 0; jj < 8; jj++)
                    acc[ii][jj] = fmaf(a[ii], b[jj], acc[ii][jj]);
        }
        __syncthreads();
    }

    #pragma unroll
    for (int ii = 0; ii < 8; ii++) {
        size_t row = (size_t)(m0 + ty + 16 * ii) * NDIM + n0;
        #pragma unroll
        for (int jj = 0; jj < 8; jj++)
            g_scratch[row + tx + 16 * jj] = acc[ii][jj];
    }
}

// ---------------------------------------------------------------------------
// Pass 2 (batched per image, fused epilogue):
//   out[img, k1, k2] = f( sum_i C[k1, i] * Y[img, i, k2] )
//   f(v) = (log(|v| + EPS) - mean) / std
// grid: (N/128, M/128, 384)
// ---------------------------------------------------------------------------
__global__ void __launch_bounds__(256) dct_pass2_kernel(float* __restrict__ Out,
                                                        const float* __restrict__ meanp,
                                                        const float* __restrict__ stdp) {
    __shared__ float As[16][128];
    __shared__ float Bs[16][128];

    const int tid = threadIdx.x;
    const int tx = tid & 15;
    const int ty = tid >> 4;
    const int m0 = blockIdx.y * 128;   // k1 tile
    const int n0 = blockIdx.x * 128;   // k2 tile
    const int img = blockIdx.z;
    const float* __restrict__ Bimg = g_scratch + (size_t)img * NDIM * NDIM;

    float acc[8][8];
    #pragma unroll
    for (int i = 0; i < 8; i++)
        #pragma unroll
        for (int j = 0; j < 8; j++) acc[i][j] = 0.0f;

    for (int kt = 0; kt < NDIM; kt += 16) {
        #pragma unroll
        for (int r = 0; r < 2; r++) {
            int idx = tid + r * 256;
            int row = idx >> 2;
            int q   = idx & 3;
            float4 v = *(const float4*)(g_basis + (size_t)(m0 + row) * NDIM + kt + q * 4);
            As[q * 4 + 0][row] = v.x;
            As[q * 4 + 1][row] = v.y;
            As[q * 4 + 2][row] = v.z;
            As[q * 4 + 3][row] = v.w;
        }
        #pragma unroll
        for (int r = 0; r < 2; r++) {
            int idx = tid + r * 256;
            int k  = idx >> 5;
            int n4 = idx & 31;
            *(float4*)(&Bs[k][n4 * 4]) =
                *(const float4*)(Bimg + (size_t)(kt + k) * NDIM + n0 + n4 * 4);
        }
        __syncthreads();

        #pragma unroll
        for (int k = 0; k < 16; k++) {
            float a[8], b[8];
            #pragma unroll
            for (int ii = 0; ii < 8; ii++) a[ii] = As[k][ty + 16 * ii];
            #pragma unroll
            for (int jj = 0; jj < 8; jj++) b[jj] = Bs[k][tx + 16 * jj];
            #pragma unroll
            for (int ii = 0; ii < 8; ii++)
                #pragma unroll
                for (int jj = 0; jj < 8; jj++)
                    acc[ii][jj] = fmaf(a[ii], b[jj], acc[ii][jj]);
        }
        __syncthreads();
    }

    const float mean = *meanp;
    const float inv_std = 1.0f / (*stdp);
    float* __restrict__ outImg = Out + (size_t)img * NDIM * NDIM;

    #pragma unroll
    for (int ii = 0; ii < 8; ii++) {
        size_t row = (size_t)(m0 + ty + 16 * ii) * NDIM + n0;
        #pragma unroll
        for (int jj = 0; jj < 8; jj++) {
            float v = acc[ii][jj];
            float l = logf(fabsf(v) + EPS);
            outImg[row + tx + 16 * jj] = (l - mean) * inv_std;
        }
    }
}

// ---------------------------------------------------------------------------
// Launch: inputs = [inputs(float32, B*C*H*W), mean(float32,1), std(float32,1)]
// ---------------------------------------------------------------------------
extern "C" void kernel_launch(void* const* d_in, const int* in_sizes, int n_in,
                              void* d_out, int out_size) {
    (void)in_sizes; (void)n_in; (void)out_size;
    const float* x     = (const float*)d_in[0];
    const float* meanp = (const float*)d_in[1];
    const float* stdp  = (const float*)d_in[2];
    float* out = (float*)d_out;

    gen_basis_kernel<<<(NDIM * NDIM + 255) / 256, 256>>>();

    // Pass 1: M = 384*256 = 98304 rows -> 768 row-tiles, 2 col-tiles.
    dct_pass1_kernel<<<dim3(98304 / 128, NDIM / 128), 256>>>(x);

    // Pass 2: per-image 256x256 output -> (2, 2, 384).
    dct_pass2_kernel<<<dim3(NDIM / 128, NDIM / 128, NIMG), 256>>>(out, meanp, stdp);
}

// round 5
// speedup vs baseline: 1.5340x; 1.5340x over previous
#include <cuda_runtime.h>
#include <math.h>
#include <cstdint>

#define NDIM 256
#define NIMG 384
#define TOTELEM (NIMG * NDIM * NDIM)
#define EPS 1e-13f

// ---------------------------------------------------------------------------
// Static device memory (no runtime allocation allowed).
// ---------------------------------------------------------------------------
__device__ float g_Yt[TOTELEM];          // pass1 out, transposed per image: [img][k2][i]
__device__ float g_bh[NDIM * NDIM];      // tf32-rounded basis C[k][i]
__device__ float g_bl[NDIM * NDIM];      // tf32 residual

// ---------------------------------------------------------------------------
// tf32 helpers
// ---------------------------------------------------------------------------
__device__ __forceinline__ float tf32f(float x) {
    uint32_t r;
    asm("cvt.rna.tf32.f32 %0, %1;" : "=r"(r) : "f"(x));
    return __uint_as_float(r);
}
__device__ __forceinline__ void split4(float4 v, float4& h, float4& l) {
    h.x = tf32f(v.x); l.x = tf32f(v.x - h.x);
    h.y = tf32f(v.y); l.y = tf32f(v.y - h.y);
    h.z = tf32f(v.z); l.z = tf32f(v.z - h.z);
    h.w = tf32f(v.w); l.w = tf32f(v.w - h.w);
}

// mma.sync m16n8k8 tf32: D += A*B (D==C in-place)
__device__ __forceinline__ void mma8(float* d, const uint32_t* a, const uint32_t* b) {
    asm volatile(
        "mma.sync.aligned.m16n8k8.row.col.f32.tf32.tf32.f32 "
        "{%0,%1,%2,%3}, {%4,%5,%6,%7}, {%8,%9}, {%0,%1,%2,%3};"
        : "+f"(d[0]), "+f"(d[1]), "+f"(d[2]), "+f"(d[3])
        : "r"(a[0]), "r"(a[1]), "r"(a[2]), "r"(a[3]), "r"(b[0]), "r"(b[1]));
}

// ---------------------------------------------------------------------------
// Basis generation + tf32 split. (2i+1)*k <= 130305 exact in fp32; /512 exact;
// cospif does exact binary period reduction.
// ---------------------------------------------------------------------------
__global__ void gen_basis_kernel() {
    int idx = blockIdx.x * blockDim.x + threadIdx.x;
    int k = idx >> 8, i = idx & 255;
    float s = (k == 0) ? 0.0625f : 0.08838834764831845f;  // sqrt(1/256), sqrt(2/256)
    float t = (float)((2 * i + 1) * k) * (1.0f / 512.0f);
    float v = s * cospif(t);
    float hi = tf32f(v);
    g_bh[idx] = hi;
    g_bl[idx] = tf32f(v - hi);
}

// ---------------------------------------------------------------------------
// SMEM layout (float units). 32-float K-chunk rows padded to 36 so fragment
// LDS bank = (4*row + col) % 32 -> conflict-free across a warp.
// ---------------------------------------------------------------------------
#define PADROW 36
#define AHI 0
#define ALO (128 * PADROW)          // 4608
#define BHI (2 * 128 * PADROW)      // 9216
#define BLO (3 * 128 * PADROW)      // 13824
#define BUFF (4 * 128 * PADROW)     // 18432 floats = 73728 B
#define SMEM_BYTES (2 * BUFF * 4)   // 147456 B, double-buffered

// ---------------------------------------------------------------------------
// Core compute for one 32-wide K chunk. Warp tile 64x32 (4x4 m16n8 tiles),
// 3 split products per fragment pair (AhBh + AhBl + AlBh).
// ---------------------------------------------------------------------------
__device__ __forceinline__ void compute_chunk(const float* __restrict__ buf,
                                              float acc[4][4][4],
                                              int wm, int wn, int grp, int qd) {
    const float* Ah = buf + AHI;
    const float* Al = buf + ALO;
    const float* Bh = buf + BHI;
    const float* Bl = buf + BLO;
    #pragma unroll
    for (int s = 0; s < 4; s++) {
        const int cc = s * 8 + qd;
        uint32_t ah[4][4], al[4][4], bh[4][2], bl[4][2];
        #pragma unroll
        for (int mt = 0; mt < 4; mt++) {
            int r = wm * 64 + mt * 16 + grp;
            ah[mt][0] = __float_as_uint(Ah[r * PADROW + cc]);
            ah[mt][1] = __float_as_uint(Ah[(r + 8) * PADROW + cc]);
            ah[mt][2] = __float_as_uint(Ah[r * PADROW + cc + 4]);
            ah[mt][3] = __float_as_uint(Ah[(r + 8) * PADROW + cc + 4]);
            al[mt][0] = __float_as_uint(Al[r * PADROW + cc]);
            al[mt][1] = __float_as_uint(Al[(r + 8) * PADROW + cc]);
            al[mt][2] = __float_as_uint(Al[r * PADROW + cc + 4]);
            al[mt][3] = __float_as_uint(Al[(r + 8) * PADROW + cc + 4]);
        }
        #pragma unroll
        for (int nt = 0; nt < 4; nt++) {
            int n = wn * 32 + nt * 8 + grp;
            bh[nt][0] = __float_as_uint(Bh[n * PADROW + cc]);
            bh[nt][1] = __float_as_uint(Bh[n * PADROW + cc + 4]);
            bl[nt][0] = __float_as_uint(Bl[n * PADROW + cc]);
            bl[nt][1] = __float_as_uint(Bl[n * PADROW + cc + 4]);
        }
        #pragma unroll
        for (int mt = 0; mt < 4; mt++)
            #pragma unroll
            for (int nt = 0; nt < 4; nt++) mma8(acc[mt][nt], ah[mt], bh[nt]);
        #pragma unroll
        for (int mt = 0; mt < 4; mt++)
            #pragma unroll
            for (int nt = 0; nt < 4; nt++) mma8(acc[mt][nt], ah[mt], bl[nt]);
        #pragma unroll
        for (int mt = 0; mt < 4; mt++)
            #pragma unroll
            for (int nt = 0; nt < 4; nt++) mma8(acc[mt][nt], al[mt], bh[nt]);
    }
}

// ---------------------------------------------------------------------------
// Pass 1: Y[m, k2] = sum_j X[m, j] * C[k2, j].  CTA tile 128m x 128n, K=256.
// A = X (split on the fly), B = pre-split basis. Output staged through an
// SMEM transpose so g_Yt[img][k2][i] stores are coalesced.
// ---------------------------------------------------------------------------
__global__ void __launch_bounds__(256, 1) dct_p1(const float* __restrict__ X) {
    extern __shared__ float smem[];
    const int tid = threadIdx.x, lane = tid & 31, wid = tid >> 5;
    const int wm = wid >> 2, wn = wid & 3, grp = lane >> 2, qd = lane & 3;
    const int n0 = blockIdx.y * 128;
    const int img = blockIdx.x >> 1, i0 = (blockIdx.x & 1) * 128;
    const int mg0 = img * NDIM + i0;          // global row base
    const int r0 = tid >> 3, q = tid & 7;     // loader mapping

    float acc[4][4][4] = {};
    float4 ra[4], rbh[4], rbl[4];

    // prologue load chunk 0
    #pragma unroll
    for (int it = 0; it < 4; it++) {
        int r = r0 + it * 32;
        ra[it]  = *(const float4*)(X + (size_t)(mg0 + r) * NDIM + q * 4);
        rbh[it] = *(const float4*)(g_bh + (size_t)(n0 + r) * NDIM + q * 4);
        rbl[it] = *(const float4*)(g_bl + (size_t)(n0 + r) * NDIM + q * 4);
    }
    #pragma unroll
    for (int it = 0; it < 4; it++) {
        int r = r0 + it * 32;
        float4 h, l; split4(ra[it], h, l);
        *(float4*)(smem + AHI + r * PADROW + q * 4) = h;
        *(float4*)(smem + ALO + r * PADROW + q * 4) = l;
        *(float4*)(smem + BHI + r * PADROW + q * 4) = rbh[it];
        *(float4*)(smem + BLO + r * PADROW + q * 4) = rbl[it];
    }
    __syncthreads();

    for (int c = 0; c < 8; c++) {
        if (c < 7) {
            #pragma unroll
            for (int it = 0; it < 4; it++) {
                int r = r0 + it * 32;
                ra[it]  = *(const float4*)(X + (size_t)(mg0 + r) * NDIM + (c + 1) * 32 + q * 4);
                rbh[it] = *(const float4*)(g_bh + (size_t)(n0 + r) * NDIM + (c + 1) * 32 + q * 4);
                rbl[it] = *(const float4*)(g_bl + (size_t)(n0 + r) * NDIM + (c + 1) * 32 + q * 4);
            }
        }
        compute_chunk(smem + (c & 1) * BUFF, acc, wm, wn, grp, qd);
        if (c < 7) {
            float* nb = smem + ((c + 1) & 1) * BUFF;
            #pragma unroll
            for (int it = 0; it < 4; it++) {
                int r = r0 + it * 32;
                float4 h, l; split4(ra[it], h, l);
                *(float4*)(nb + AHI + r * PADROW + q * 4) = h;
                *(float4*)(nb + ALO + r * PADROW + q * 4) = l;
                *(float4*)(nb + BHI + r * PADROW + q * 4) = rbh[it];
                *(float4*)(nb + BLO + r * PADROW + q * 4) = rbl[it];
            }
        }
        __syncthreads();
    }

    // Transpose through SMEM: T[n][m], stride 132 -> conflict-free ((8qd+grp)).
    float* T = smem;
    #pragma unroll
    for (int mt = 0; mt < 4; mt++)
        #pragma unroll
        for (int nt = 0; nt < 4; nt++) {
            int m = wm * 64 + mt * 16 + grp;
            int n = wn * 32 + nt * 8 + 2 * qd;
            T[(size_t)n * 132 + m]           = acc[mt][nt][0];
            T[(size_t)(n + 1) * 132 + m]     = acc[mt][nt][1];
            T[(size_t)n * 132 + m + 8]       = acc[mt][nt][2];
            T[(size_t)(n + 1) * 132 + m + 8] = acc[mt][nt][3];
        }
    __syncthreads();

    float* dst = g_Yt + (size_t)img * NDIM * NDIM;
    #pragma unroll
    for (int rr = 0; rr < 16; rr++) {
        int n = wid * 16 + rr;
        float4 v = *(float4*)&T[(size_t)n * 132 + lane * 4];
        *(float4*)(dst + (size_t)(n0 + n) * NDIM + i0 + lane * 4) = v;
    }
}

// ---------------------------------------------------------------------------
// Pass 2: out[img, k1, k2] = f( sum_i C[k1, i] * Yt[img, k2, i] ).
// A = pre-split basis rows k1; B = Yt rows k2 (split on the fly).
// Fused log/affine epilogue, direct float2 stores (32B segments).
// ---------------------------------------------------------------------------
__global__ void __launch_bounds__(256, 1) dct_p2(float* __restrict__ Out,
                                                 const float* __restrict__ meanp,
                                                 const float* __restrict__ stdp) {
    extern __shared__ float smem[];
    const int tid = threadIdx.x, lane = tid & 31, wid = tid >> 5;
    const int wm = wid >> 2, wn = wid & 3, grp = lane >> 2, qd = lane & 3;
    const int m0 = blockIdx.y * 128;    // k1 tile
    const int n0 = blockIdx.x * 128;    // k2 tile
    const int img = blockIdx.z;
    const float* Yt = g_Yt + (size_t)img * NDIM * NDIM;
    const int r0 = tid >> 3, q = tid & 7;

    float acc[4][4][4] = {};
    float4 rah[4], ral[4], rb[4];

    #pragma unroll
    for (int it = 0; it < 4; it++) {
        int r = r0 + it * 32;
        rah[it] = *(const float4*)(g_bh + (size_t)(m0 + r) * NDIM + q * 4);
        ral[it] = *(const float4*)(g_bl + (size_t)(m0 + r) * NDIM + q * 4);
        rb[it]  = *(const float4*)(Yt + (size_t)(n0 + r) * NDIM + q * 4);
    }
    #pragma unroll
    for (int it = 0; it < 4; it++) {
        int r = r0 + it * 32;
        float4 h, l; split4(rb[it], h, l);
        *(float4*)(smem + AHI + r * PADROW + q * 4) = rah[it];
        *(float4*)(smem + ALO + r * PADROW + q * 4) = ral[it];
        *(float4*)(smem + BHI + r * PADROW + q * 4) = h;
        *(float4*)(smem + BLO + r * PADROW + q * 4) = l;
    }
    __syncthreads();

    for (int c = 0; c < 8; c++) {
        if (c < 7) {
            #pragma unroll
            for (int it = 0; it < 4; it++) {
                int r = r0 + it * 32;
                rah[it] = *(const float4*)(g_bh + (size_t)(m0 + r) * NDIM + (c + 1) * 32 + q * 4);
                ral[it] = *(const float4*)(g_bl + (size_t)(m0 + r) * NDIM + (c + 1) * 32 + q * 4);
                rb[it]  = *(const float4*)(Yt + (size_t)(n0 + r) * NDIM + (c + 1) * 32 + q * 4);
            }
        }
        compute_chunk(smem + (c & 1) * BUFF, acc, wm, wn, grp, qd);
        if (c < 7) {
            float* nb = smem + ((c + 1) & 1) * BUFF;
            #pragma unroll
            for (int it = 0; it < 4; it++) {
                int r = r0 + it * 32;
                float4 h, l; split4(rb[it], h, l);
                *(float4*)(nb + AHI + r * PADROW + q * 4) = rah[it];
                *(float4*)(nb + ALO + r * PADROW + q * 4) = ral[it];
                *(float4*)(nb + BHI + r * PADROW + q * 4) = h;
                *(float4*)(nb + BLO + r * PADROW + q * 4) = l;
            }
        }
        __syncthreads();
    }

    const float mean = *meanp;
    const float istd = 1.0f / (*stdp);
    float* o = Out + (size_t)img * NDIM * NDIM;
    #pragma unroll
    for (int mt = 0; mt < 4; mt++)
        #pragma unroll
        for (int nt = 0; nt < 4; nt++) {
            int m = m0 + wm * 64 + mt * 16 + grp;
            int n = n0 + wn * 32 + nt * 8 + 2 * qd;
            float2 v;
            v.x = (logf(fabsf(acc[mt][nt][0]) + EPS) - mean) * istd;
            v.y = (logf(fabsf(acc[mt][nt][1]) + EPS) - mean) * istd;
            *(float2*)(o + (size_t)m * NDIM + n) = v;
            v.x = (logf(fabsf(acc[mt][nt][2]) + EPS) - mean) * istd;
            v.y = (logf(fabsf(acc[mt][nt][3]) + EPS) - mean) * istd;
            *(float2*)(o + (size_t)(m + 8) * NDIM + n) = v;
        }
}

// ---------------------------------------------------------------------------
extern "C" void kernel_launch(void* const* d_in, const int* in_sizes, int n_in,
                              void* d_out, int out_size) {
    (void)in_sizes; (void)n_in; (void)out_size;
    const float* x     = (const float*)d_in[0];
    const float* meanp = (const float*)d_in[1];
    const float* stdp  = (const float*)d_in[2];
    float* out = (float*)d_out;

    cudaFuncSetAttribute(dct_p1, cudaFuncAttributeMaxDynamicSharedMemorySize, SMEM_BYTES);
    cudaFuncSetAttribute(dct_p2, cudaFuncAttributeMaxDynamicSharedMemorySize, SMEM_BYTES);

    gen_basis_kernel<<<256, 256>>>();
    dct_p1<<<dim3(768, 2), 256, SMEM_BYTES>>>(x);
    dct_p2<<<dim3(2, 2, NIMG), 256, SMEM_BYTES>>>(out, meanp, stdp);
}

// round 6
// speedup vs baseline: 1.5879x; 1.0351x over previous
#include <cuda_runtime.h>
#include <math.h>
#include <cstdint>

#define NDIM 256
#define NIMG 384
#define TOTELEM (NIMG * NDIM * NDIM)
#define EPS 1e-13f

// ---------------------------------------------------------------------------
// Static device memory (no runtime allocation allowed).
// ---------------------------------------------------------------------------
__device__ float g_Yt[TOTELEM];          // pass1 out, transposed per image: [img][k2][i]
__device__ float g_b[NDIM * NDIM];       // fp32 basis C[k][i]

// ---------------------------------------------------------------------------
// Helpers
// ---------------------------------------------------------------------------
__device__ __forceinline__ uint32_t smem_u32(const void* p) {
    uint32_t a;
    asm("{ .reg .u64 t; cvta.to.shared.u64 t, %1; cvt.u32.u64 %0, t; }" : "=r"(a) : "l"(p));
    return a;
}
__device__ __forceinline__ float tf32f(float x) {
    uint32_t r;
    asm("cvt.rna.tf32.f32 %0, %1;" : "=r"(r) : "f"(x));
    return __uint_as_float(r);
}
// mma.sync m16n8k8 tf32: D += A*B (in-place)
__device__ __forceinline__ void mma8(float* d, const uint32_t* a, const uint32_t* b) {
    asm volatile(
        "mma.sync.aligned.m16n8k8.row.col.f32.tf32.tf32.f32 "
        "{%0,%1,%2,%3}, {%4,%5,%6,%7}, {%8,%9}, {%0,%1,%2,%3};"
        : "+f"(d[0]), "+f"(d[1]), "+f"(d[2]), "+f"(d[3])
        : "r"(a[0]), "r"(a[1]), "r"(a[2]), "r"(a[3]), "r"(b[0]), "r"(b[1]));
}
#define CP16(dst, src) asm volatile("cp.async.cg.shared.global [%0], [%1], 16;" :: "r"(dst), "l"(src))
#define CP_COMMIT()    asm volatile("cp.async.commit_group;" ::: "memory")
#define CP_WAIT0()     asm volatile("cp.async.wait_group 0;" ::: "memory")

// ---------------------------------------------------------------------------
// Basis generation (raw fp32). (2i+1)*k <= 130305 exact in fp32; /512 exact.
// ---------------------------------------------------------------------------
__global__ void gen_basis_kernel() {
    int idx = blockIdx.x * blockDim.x + threadIdx.x;
    int k = idx >> 8, i = idx & 255;
    float s = (k == 0) ? 0.0625f : 0.08838834764831845f;  // sqrt(1/256), sqrt(2/256)
    float t = (float)((2 * i + 1) * k) * (1.0f / 512.0f);
    g_b[idx] = s * cospif(t);
}

// ---------------------------------------------------------------------------
// SMEM: raw fp32 staging, rows of a 32-wide K chunk padded to 36 floats.
// One stage = A(128x36) + B(128x36) = 9216 floats; double-buffered.
// ---------------------------------------------------------------------------
#define PADROW 36
#define BOFF   (128 * PADROW)        // 4608 floats
#define STAGE  (2 * 128 * PADROW)    // 9216 floats
#define SMEM_BYTES (2 * STAGE * 4)   // 73728 B -> 2 CTAs/SM

// ---------------------------------------------------------------------------
// One 32-wide K chunk: warp tile 64x32 (4x4 m16n8 tiles), raw fp32 fragments
// split to tf32 hi/lo in registers, 3 products (AhBh + AhBl + AlBh).
// Scalar LDS addresses are (4*grp + qd + const) mod 32 -> conflict-free.
// ---------------------------------------------------------------------------
__device__ __forceinline__ void compute_chunk(const float* __restrict__ buf,
                                              float acc[4][4][4],
                                              int wm, int wn, int grp, int qd) {
    const float* __restrict__ A = buf;
    const float* __restrict__ B = buf + BOFF;
    #pragma unroll
    for (int s = 0; s < 4; s++) {
        const int cc = s * 8 + qd;
        uint32_t bh[4][2], bl[4][2];
        #pragma unroll
        for (int nt = 0; nt < 4; nt++) {
            int n = wn * 32 + nt * 8 + grp;
            float v0 = B[n * PADROW + cc];
            float v1 = B[n * PADROW + cc + 4];
            float h0 = tf32f(v0), h1 = tf32f(v1);
            bh[nt][0] = __float_as_uint(h0);
            bh[nt][1] = __float_as_uint(h1);
            bl[nt][0] = __float_as_uint(tf32f(v0 - h0));
            bl[nt][1] = __float_as_uint(tf32f(v1 - h1));
        }
        #pragma unroll
        for (int mt = 0; mt < 4; mt++) {
            int r = wm * 64 + mt * 16 + grp;
            float v0 = A[r * PADROW + cc];
            float v1 = A[(r + 8) * PADROW + cc];
            float v2 = A[r * PADROW + cc + 4];
            float v3 = A[(r + 8) * PADROW + cc + 4];
            float h0 = tf32f(v0), h1 = tf32f(v1), h2 = tf32f(v2), h3 = tf32f(v3);
            uint32_t ah[4] = { __float_as_uint(h0), __float_as_uint(h1),
                               __float_as_uint(h2), __float_as_uint(h3) };
            uint32_t al[4] = { __float_as_uint(tf32f(v0 - h0)), __float_as_uint(tf32f(v1 - h1)),
                               __float_as_uint(tf32f(v2 - h2)), __float_as_uint(tf32f(v3 - h3)) };
            #pragma unroll
            for (int nt = 0; nt < 4; nt++) mma8(acc[mt][nt], ah, bh[nt]);
            #pragma unroll
            for (int nt = 0; nt < 4; nt++) mma8(acc[mt][nt], ah, bl[nt]);
            #pragma unroll
            for (int nt = 0; nt < 4; nt++) mma8(acc[mt][nt], al, bh[nt]);
        }
    }
}

// loader: 256 threads, each stages 4 rows of A and 4 rows of B (16B per row)
__device__ __forceinline__ void stage_chunk(uint32_t sb, int buf,
                                            const float* __restrict__ Asrc, int astride,
                                            const float* __restrict__ Bsrc, int bstride,
                                            int col0, int r0, int q) {
    #pragma unroll
    for (int it = 0; it < 4; it++) {
        int r = r0 + it * 32;
        CP16(sb + (buf * STAGE + r * PADROW + q * 4) * 4,
             Asrc + (size_t)r * astride + col0 + q * 4);
        CP16(sb + (buf * STAGE + BOFF + r * PADROW + q * 4) * 4,
             Bsrc + (size_t)r * bstride + col0 + q * 4);
    }
}

// ---------------------------------------------------------------------------
// Pass 1: Y[m, k2] = sum_j X[m, j] * C[k2, j].  CTA tile 128m x 128n, K=256.
// Output transposed per image through SMEM: g_Yt[img][k2][i].
// ---------------------------------------------------------------------------
__global__ void __launch_bounds__(256, 2) dct_p1(const float* __restrict__ X) {
    extern __shared__ float smem[];
    const uint32_t sb = smem_u32(smem);
    const int tid = threadIdx.x, lane = tid & 31, wid = tid >> 5;
    const int wm = wid >> 2, wn = wid & 3, grp = lane >> 2, qd = lane & 3;
    const int n0 = blockIdx.y * 128;
    const int img = blockIdx.x >> 1, i0 = (blockIdx.x & 1) * 128;
    const float* Arow = X + (size_t)(img * NDIM + i0) * NDIM;
    const float* Brow = g_b + (size_t)n0 * NDIM;
    const int r0 = tid >> 3, q = tid & 7;

    float acc[4][4][4] = {};

    stage_chunk(sb, 0, Arow, NDIM, Brow, NDIM, 0, r0, q);
    CP_COMMIT();

    for (int c = 0; c < 8; c++) {
        CP_WAIT0();
        __syncthreads();
        if (c < 7) {
            stage_chunk(sb, (c + 1) & 1, Arow, NDIM, Brow, NDIM, (c + 1) * 32, r0, q);
            CP_COMMIT();
        }
        compute_chunk(smem + (c & 1) * STAGE, acc, wm, wn, grp, qd);
    }
    __syncthreads();

    // Transpose through SMEM (stride 132, conflict-free), coalesced store.
    float* T = smem;
    #pragma unroll
    for (int mt = 0; mt < 4; mt++)
        #pragma unroll
        for (int nt = 0; nt < 4; nt++) {
            int m = wm * 64 + mt * 16 + grp;
            int n = wn * 32 + nt * 8 + 2 * qd;
            T[(size_t)n * 132 + m]           = acc[mt][nt][0];
            T[(size_t)(n + 1) * 132 + m]     = acc[mt][nt][1];
            T[(size_t)n * 132 + m + 8]       = acc[mt][nt][2];
            T[(size_t)(n + 1) * 132 + m + 8] = acc[mt][nt][3];
        }
    __syncthreads();

    float* dst = g_Yt + (size_t)img * NDIM * NDIM;
    #pragma unroll
    for (int rr = 0; rr < 16; rr++) {
        int n = wid * 16 + rr;
        float4 v = *(float4*)&T[(size_t)n * 132 + lane * 4];
        *(float4*)(dst + (size_t)(n0 + n) * NDIM + i0 + lane * 4) = v;
    }
}

// ---------------------------------------------------------------------------
// Pass 2: out[img, k1, k2] = f( sum_i C[k1, i] * Yt[img, k2, i] ).
// A = basis rows k1, B = Yt rows k2 (both raw, split at fragment load).
// Fused __log2f epilogue, direct float2 stores.
// ---------------------------------------------------------------------------
__global__ void __launch_bounds__(256, 2) dct_p2(float* __restrict__ Out,
                                                 const float* __restrict__ meanp,
                                                 const float* __restrict__ stdp) {
    extern __shared__ float smem[];
    const uint32_t sb = smem_u32(smem);
    const int tid = threadIdx.x, lane = tid & 31, wid = tid >> 5;
    const int wm = wid >> 2, wn = wid & 3, grp = lane >> 2, qd = lane & 3;
    const int m0 = blockIdx.y * 128;    // k1 tile
    const int n0 = blockIdx.x * 128;    // k2 tile
    const int img = blockIdx.z;
    const float* Arow = g_b + (size_t)m0 * NDIM;
    const float* Brow = g_Yt + (size_t)img * NDIM * NDIM + (size_t)n0 * NDIM;
    const int r0 = tid >> 3, q = tid & 7;

    float acc[4][4][4] = {};

    stage_chunk(sb, 0, Arow, NDIM, Brow, NDIM, 0, r0, q);
    CP_COMMIT();

    for (int c = 0; c < 8; c++) {
        CP_WAIT0();
        __syncthreads();
        if (c < 7) {
            stage_chunk(sb, (c + 1) & 1, Arow, NDIM, Brow, NDIM, (c + 1) * 32, r0, q);
            CP_COMMIT();
        }
        compute_chunk(smem + (c & 1) * STAGE, acc, wm, wn, grp, qd);
    }

    const float mean = *meanp;
    const float istd = 1.0f / (*stdp);
    const float sa = 0.69314718055994531f * istd;   // ln2 * istd
    const float sbias = -mean * istd;
    float* o = Out + (size_t)img * NDIM * NDIM;
    #pragma unroll
    for (int mt = 0; mt < 4; mt++)
        #pragma unroll
        for (int nt = 0; nt < 4; nt++) {
            int m = m0 + wm * 64 + mt * 16 + grp;
            int n = n0 + wn * 32 + nt * 8 + 2 * qd;
            float2 v;
            v.x = fmaf(__log2f(fabsf(acc[mt][nt][0]) + EPS), sa, sbias);
            v.y = fmaf(__log2f(fabsf(acc[mt][nt][1]) + EPS), sa, sbias);
            *(float2*)(o + (size_t)m * NDIM + n) = v;
            v.x = fmaf(__log2f(fabsf(acc[mt][nt][2]) + EPS), sa, sbias);
            v.y = fmaf(__log2f(fabsf(acc[mt][nt][3]) + EPS), sa, sbias);
            *(float2*)(o + (size_t)(m + 8) * NDIM + n) = v;
        }
}

// ---------------------------------------------------------------------------
extern "C" void kernel_launch(void* const* d_in, const int* in_sizes, int n_in,
                              void* d_out, int out_size) {
    (void)in_sizes; (void)n_in; (void)out_size;
    const float* x     = (const float*)d_in[0];
    const float* meanp = (const float*)d_in[1];
    const float* stdp  = (const float*)d_in[2];
    float* out = (float*)d_out;

    cudaFuncSetAttribute(dct_p1, cudaFuncAttributeMaxDynamicSharedMemorySize, SMEM_BYTES);
    cudaFuncSetAttribute(dct_p2, cudaFuncAttributeMaxDynamicSharedMemorySize, SMEM_BYTES);

    gen_basis_kernel<<<256, 256>>>();
    dct_p1<<<dim3(768, 2), 256, SMEM_BYTES>>>(x);
    dct_p2<<<dim3(2, 2, NIMG), 256, SMEM_BYTES>>>(out, meanp, stdp);
}

// round 7
// speedup vs baseline: 2.6246x; 1.6529x over previous
#include <cuda_runtime.h>
#include <math.h>
#include <cstdint>

#define NDIM 256
#define HDIM 128
#define NIMG 384
#define TOTELEM (NIMG * NDIM * NDIM)
#define EPS 1e-13f

// ---------------------------------------------------------------------------
// Static device memory (no runtime allocation allowed).
// ---------------------------------------------------------------------------
__device__ float g_Yt[TOTELEM];          // pass1 out, transposed per image: [img][k2][i]
__device__ float g_be[HDIM * HDIM];      // even half-basis Ce[r][j]
__device__ float g_bo[HDIM * HDIM];      // odd  half-basis Co[r][j]

// ---------------------------------------------------------------------------
// Helpers
// ---------------------------------------------------------------------------
__device__ __forceinline__ uint32_t smem_u32(const void* p) {
    uint32_t a;
    asm("{ .reg .u64 t; cvta.to.shared.u64 t, %1; cvt.u32.u64 %0, t; }" : "=r"(a) : "l"(p));
    return a;
}
__device__ __forceinline__ float tf32f(float x) {
    uint32_t r;
    asm("cvt.rna.tf32.f32 %0, %1;" : "=r"(r) : "f"(x));
    return __uint_as_float(r);
}
// mma.sync m16n8k8 tf32: D += A*B (in-place)
__device__ __forceinline__ void mma8(float* d, const uint32_t* a, const uint32_t* b) {
    asm volatile(
        "mma.sync.aligned.m16n8k8.row.col.f32.tf32.tf32.f32 "
        "{%0,%1,%2,%3}, {%4,%5,%6,%7}, {%8,%9}, {%0,%1,%2,%3};"
        : "+f"(d[0]), "+f"(d[1]), "+f"(d[2]), "+f"(d[3])
        : "r"(a[0]), "r"(a[1]), "r"(a[2]), "r"(a[3]), "r"(b[0]), "r"(b[1]));
}
#define CP16(dst, src) asm volatile("cp.async.cg.shared.global [%0], [%1], 16;" :: "r"(dst), "l"(src))
#define CP_COMMIT()    asm volatile("cp.async.commit_group;" ::: "memory")
#define CP_WAIT0()     asm volatile("cp.async.wait_group 0;" ::: "memory")

// ---------------------------------------------------------------------------
// Half-basis generation.
//   Ce[r][j] = s_{2r}  * cos(pi*(2j+1)*r/256)        (s = sqrt(1/256) if r==0 else sqrt(2/256))
//   Co[r][j] = sqrt(2/256) * cos(pi*(2j+1)*(2r+1)/512)
// Integer products <= 65025: exact in fp32; /256, /512 exact; cospif exact reduction.
// ---------------------------------------------------------------------------
__global__ void gen_basis_kernel() {
    int idx = blockIdx.x * blockDim.x + threadIdx.x;   // 0..32767
    int r = (idx >> 7) & 127, j = idx & 127;
    if (idx < 16384) {
        float s = (r == 0) ? 0.0625f : 0.08838834764831845f;
        g_be[r * HDIM + j] = s * cospif((float)((2 * j + 1) * r) * (1.0f / 256.0f));
    } else {
        g_bo[r * HDIM + j] = 0.08838834764831845f *
            cospif((float)((2 * j + 1) * (2 * r + 1)) * (1.0f / 512.0f));
    }
}

// ---------------------------------------------------------------------------
// SMEM: raw fp32 staging, rows of a 32-wide K chunk padded to 36 floats.
// One stage = M-side(128x36) + N-side(128x36); double-buffered. 73728 B -> occ 2.
// ---------------------------------------------------------------------------
#define PADROW 36
#define BOFF   (128 * PADROW)
#define STAGE  (2 * 128 * PADROW)
#define SMEM_BYTES (2 * STAGE * 4)

// ---------------------------------------------------------------------------
// One 32-wide K chunk: warp tile 64x32 (4x4 m16n8 tiles), raw fp32 fragments
// split to tf32 hi/lo in registers, 3 products (AhBh + AhBl + AlBh).
// ---------------------------------------------------------------------------
__device__ __forceinline__ void compute_chunk(const float* __restrict__ buf,
                                              float acc[4][4][4],
                                              int wm, int wn, int grp, int qd) {
    const float* __restrict__ A = buf;
    const float* __restrict__ B = buf + BOFF;
    #pragma unroll
    for (int s = 0; s < 4; s++) {
        const int cc = s * 8 + qd;
        uint32_t bh[4][2], bl[4][2];
        #pragma unroll
        for (int nt = 0; nt < 4; nt++) {
            int n = wn * 32 + nt * 8 + grp;
            float v0 = B[n * PADROW + cc];
            float v1 = B[n * PADROW + cc + 4];
            float h0 = tf32f(v0), h1 = tf32f(v1);
            bh[nt][0] = __float_as_uint(h0);
            bh[nt][1] = __float_as_uint(h1);
            bl[nt][0] = __float_as_uint(tf32f(v0 - h0));
            bl[nt][1] = __float_as_uint(tf32f(v1 - h1));
        }
        #pragma unroll
        for (int mt = 0; mt < 4; mt++) {
            int r = wm * 64 + mt * 16 + grp;
            float v0 = A[r * PADROW + cc];
            float v1 = A[(r + 8) * PADROW + cc];
            float v2 = A[r * PADROW + cc + 4];
            float v3 = A[(r + 8) * PADROW + cc + 4];
            float h0 = tf32f(v0), h1 = tf32f(v1), h2 = tf32f(v2), h3 = tf32f(v3);
            uint32_t ah[4] = { __float_as_uint(h0), __float_as_uint(h1),
                               __float_as_uint(h2), __float_as_uint(h3) };
            uint32_t al[4] = { __float_as_uint(tf32f(v0 - h0)), __float_as_uint(tf32f(v1 - h1)),
                               __float_as_uint(tf32f(v2 - h2)), __float_as_uint(tf32f(v3 - h3)) };
            #pragma unroll
            for (int nt = 0; nt < 4; nt++) mma8(acc[mt][nt], ah, bh[nt]);
            #pragma unroll
            for (int nt = 0; nt < 4; nt++) mma8(acc[mt][nt], ah, bl[nt]);
            #pragma unroll
            for (int nt = 0; nt < 4; nt++) mma8(acc[mt][nt], al, bh[nt]);
        }
    }
}

// Fold prefetch: f[it][e] = src[r][col0+q*4+e] +/- src[r][255-(col0+q*4+e)]
__device__ __forceinline__ void ldg_fold(float f[4][4], const float* __restrict__ src,
                                         int col0, int r0, int q, float sgn) {
    #pragma unroll
    for (int it = 0; it < 4; it++) {
        int r = r0 + it * 32;
        float4 a = *(const float4*)(src + (size_t)r * NDIM + col0 + q * 4);
        float4 b = *(const float4*)(src + (size_t)r * NDIM + 252 - col0 - q * 4);
        f[it][0] = fmaf(sgn, b.w, a.x);
        f[it][1] = fmaf(sgn, b.z, a.y);
        f[it][2] = fmaf(sgn, b.y, a.z);
        f[it][3] = fmaf(sgn, b.x, a.w);
    }
}
__device__ __forceinline__ void sts_fold(float* __restrict__ dst, const float f[4][4],
                                         int r0, int q) {
    #pragma unroll
    for (int it = 0; it < 4; it++) {
        int r = r0 + it * 32;
        *(float4*)(dst + r * PADROW + q * 4) = make_float4(f[it][0], f[it][1], f[it][2], f[it][3]);
    }
}
// Basis staging via cp.async (HDIM-stride matrix)
__device__ __forceinline__ void stage_basis(uint32_t sb, int buf, int regionOff,
                                            const float* __restrict__ Bmat,
                                            int col0, int r0, int q) {
    #pragma unroll
    for (int it = 0; it < 4; it++) {
        int r = r0 + it * 32;
        CP16(sb + (buf * STAGE + regionOff + r * PADROW + q * 4) * 4,
             Bmat + (size_t)r * HDIM + col0 + q * 4);
    }
}

// ---------------------------------------------------------------------------
// Pass 1: Y[m, 2r+par] = sum_{j<128} fold_par(X)[m, j] * Cpar[r, j].
// CTA: 128 m-rows x 128 outputs (one parity), K = 128 (4 chunks).
// Output transposed per image: g_Yt[img][2n+par][i].
// ---------------------------------------------------------------------------
__global__ void __launch_bounds__(256, 2) dct_p1(const float* __restrict__ X) {
    extern __shared__ float smem[];
    const uint32_t sb = smem_u32(smem);
    const int tid = threadIdx.x, lane = tid & 31, wid = tid >> 5;
    const int wm = wid >> 2, wn = wid & 3, grp = lane >> 2, qd = lane & 3;
    const int par = blockIdx.y;
    const int img = blockIdx.x >> 1, i0 = (blockIdx.x & 1) * 128;
    const float* Arow = X + (size_t)(img * NDIM + i0) * NDIM;
    const float* Bmat = par ? g_bo : g_be;
    const float sgn = par ? -1.0f : 1.0f;
    const int r0 = tid >> 3, q = tid & 7;

    float acc[4][4][4] = {};
    float fold[4][4];

    ldg_fold(fold, Arow, 0, r0, q, sgn);
    stage_basis(sb, 0, BOFF, Bmat, 0, r0, q);
    CP_COMMIT();

    for (int c = 0; c < 4; c++) {
        CP_WAIT0();
        __syncthreads();                       // prior compute done; buffers free
        sts_fold(smem + (c & 1) * STAGE, fold, r0, q);
        if (c < 3) {
            ldg_fold(fold, Arow, (c + 1) * 32, r0, q, sgn);
            stage_basis(sb, (c + 1) & 1, BOFF, Bmat, (c + 1) * 32, r0, q);
            CP_COMMIT();
        }
        __syncthreads();
        compute_chunk(smem + (c & 1) * STAGE, acc, wm, wn, grp, qd);
    }
    __syncthreads();

    // Transpose through SMEM (stride 132, conflict-free), coalesced store.
    float* T = smem;
    #pragma unroll
    for (int mt = 0; mt < 4; mt++)
        #pragma unroll
        for (int nt = 0; nt < 4; nt++) {
            int m = wm * 64 + mt * 16 + grp;
            int n = wn * 32 + nt * 8 + 2 * qd;
            T[(size_t)n * 132 + m]           = acc[mt][nt][0];
            T[(size_t)(n + 1) * 132 + m]     = acc[mt][nt][1];
            T[(size_t)n * 132 + m + 8]       = acc[mt][nt][2];
            T[(size_t)(n + 1) * 132 + m + 8] = acc[mt][nt][3];
        }
    __syncthreads();

    float* dst = g_Yt + (size_t)img * NDIM * NDIM;
    #pragma unroll
    for (int rr = 0; rr < 16; rr++) {
        int n = wid * 16 + rr;
        float4 v = *(float4*)&T[(size_t)n * 132 + lane * 4];
        *(float4*)(dst + (size_t)(2 * n + par) * NDIM + i0 + lane * 4) = v;
    }
}

// ---------------------------------------------------------------------------
// Pass 2: out[img, 2r+par, k2] = f( sum_{j<128} Cpar[r, j] * fold_par(Yt)[k2, j] ).
// A = half-basis (cp.async), B = folded Yt rows. Fused __log2f epilogue.
// ---------------------------------------------------------------------------
__global__ void __launch_bounds__(256, 2) dct_p2(float* __restrict__ Out,
                                                 const float* __restrict__ meanp,
                                                 const float* __restrict__ stdp) {
    extern __shared__ float smem[];
    const uint32_t sb = smem_u32(smem);
    const int tid = threadIdx.x, lane = tid & 31, wid = tid >> 5;
    const int wm = wid >> 2, wn = wid & 3, grp = lane >> 2, qd = lane & 3;
    const int n0 = blockIdx.x * 128;    // k2 tile
    const int par = blockIdx.y;
    const int img = blockIdx.z;
    const float* Brow = g_Yt + (size_t)img * NDIM * NDIM + (size_t)n0 * NDIM;
    const float* Amat = par ? g_bo : g_be;
    const float sgn = par ? -1.0f : 1.0f;
    const int r0 = tid >> 3, q = tid & 7;

    float acc[4][4][4] = {};
    float fold[4][4];

    ldg_fold(fold, Brow, 0, r0, q, sgn);
    stage_basis(sb, 0, 0, Amat, 0, r0, q);
    CP_COMMIT();

    for (int c = 0; c < 4; c++) {
        CP_WAIT0();
        __syncthreads();
        sts_fold(smem + (c & 1) * STAGE + BOFF, fold, r0, q);
        if (c < 3) {
            ldg_fold(fold, Brow, (c + 1) * 32, r0, q, sgn);
            stage_basis(sb, (c + 1) & 1, 0, Amat, (c + 1) * 32, r0, q);
            CP_COMMIT();
        }
        __syncthreads();
        compute_chunk(smem + (c & 1) * STAGE, acc, wm, wn, grp, qd);
    }

    const float mean = *meanp;
    const float istd = 1.0f / (*stdp);
    const float sa = 0.69314718055994531f * istd;   // ln2 * istd
    const float sbias = -mean * istd;
    float* o = Out + (size_t)img * NDIM * NDIM;
    #pragma unroll
    for (int mt = 0; mt < 4; mt++)
        #pragma unroll
        for (int nt = 0; nt < 4; nt++) {
            int m = wm * 64 + mt * 16 + grp;                 // local half-row
            int n = n0 + wn * 32 + nt * 8 + 2 * qd;
            float2 v;
            v.x = fmaf(__log2f(fabsf(acc[mt][nt][0]) + EPS), sa, sbias);
            v.y = fmaf(__log2f(fabsf(acc[mt][nt][1]) + EPS), sa, sbias);
            *(float2*)(o + (size_t)(2 * m + par) * NDIM + n) = v;
            v.x = fmaf(__log2f(fabsf(acc[mt][nt][2]) + EPS), sa, sbias);
            v.y = fmaf(__log2f(fabsf(acc[mt][nt][3]) + EPS), sa, sbias);
            *(float2*)(o + (size_t)(2 * (m + 8) + par) * NDIM + n) = v;
        }
}

// ---------------------------------------------------------------------------
extern "C" void kernel_launch(void* const* d_in, const int* in_sizes, int n_in,
                              void* d_out, int out_size) {
    (void)in_sizes; (void)n_in; (void)out_size;
    const float* x     = (const float*)d_in[0];
    const float* meanp = (const float*)d_in[1];
    const float* stdp  = (const float*)d_in[2];
    float* out = (float*)d_out;

    cudaFuncSetAttribute(dct_p1, cudaFuncAttributeMaxDynamicSharedMemorySize, SMEM_BYTES);
    cudaFuncSetAttribute(dct_p2, cudaFuncAttributeMaxDynamicSharedMemorySize, SMEM_BYTES);

    gen_basis_kernel<<<128, 256>>>();
    dct_p1<<<dim3(768, 2), 256, SMEM_BYTES>>>(x);
    dct_p2<<<dim3(2, 2, NIMG), 256, SMEM_BYTES>>>(out, meanp, stdp);
}

// round 8
// speedup vs baseline: 2.6722x; 1.0181x over previous
#include <cuda_runtime.h>
#include <math.h>
#include <cstdint>

#define NDIM 256
#define HDIM 128
#define NIMG 384
#define TOTELEM (NIMG * NDIM * NDIM)
#define EPS 1e-13f

// ---------------------------------------------------------------------------
// Static device memory (no runtime allocation allowed).
// ---------------------------------------------------------------------------
__device__ float g_Yt[TOTELEM];          // pass1 out, transposed per image: [img][k2][i]
__device__ float g_be[HDIM * HDIM];      // even half-basis Ce[r][j]
__device__ float g_bo[HDIM * HDIM];      // odd  half-basis Co[r][j]

// ---------------------------------------------------------------------------
// Helpers
// ---------------------------------------------------------------------------
__device__ __forceinline__ uint32_t smem_u32(const void* p) {
    uint32_t a;
    asm("{ .reg .u64 t; cvta.to.shared.u64 t, %1; cvt.u32.u64 %0, t; }" : "=r"(a) : "l"(p));
    return a;
}
__device__ __forceinline__ float tf32f(float x) {
    uint32_t r;
    asm("cvt.rna.tf32.f32 %0, %1;" : "=r"(r) : "f"(x));
    return __uint_as_float(r);
}
// mma.sync m16n8k8 tf32: D += A*B (in-place)
__device__ __forceinline__ void mma8(float* d, const uint32_t* a, const uint32_t* b) {
    asm volatile(
        "mma.sync.aligned.m16n8k8.row.col.f32.tf32.tf32.f32 "
        "{%0,%1,%2,%3}, {%4,%5,%6,%7}, {%8,%9}, {%0,%1,%2,%3};"
        : "+f"(d[0]), "+f"(d[1]), "+f"(d[2]), "+f"(d[3])
        : "r"(a[0]), "r"(a[1]), "r"(a[2]), "r"(a[3]), "r"(b[0]), "r"(b[1]));
}
#define CP16(dst, src) asm volatile("cp.async.cg.shared.global [%0], [%1], 16;" :: "r"(dst), "l"(src))
#define CP_COMMIT()    asm volatile("cp.async.commit_group;" ::: "memory")
#define CP_WAIT0()     asm volatile("cp.async.wait_group 0;" ::: "memory")

// streaming (evict-first) float2 store: output is never re-read; keep L2 for Yt
__device__ __forceinline__ void stcs2(float* p, float2 v) {
    asm volatile("st.global.cs.v2.f32 [%0], {%1, %2};" :: "l"(p), "f"(v.x), "f"(v.y) : "memory");
}

// ---------------------------------------------------------------------------
// Half-basis generation.
//   Ce[r][j] = s_{2r}  * cos(pi*(2j+1)*r/256)
//   Co[r][j] = sqrt(2/256) * cos(pi*(2j+1)*(2r+1)/512)
// ---------------------------------------------------------------------------
__global__ void gen_basis_kernel() {
    int idx = blockIdx.x * blockDim.x + threadIdx.x;   // 0..32767
    int r = (idx >> 7) & 127, j = idx & 127;
    if (idx < 16384) {
        float s = (r == 0) ? 0.0625f : 0.08838834764831845f;
        g_be[r * HDIM + j] = s * cospif((float)((2 * j + 1) * r) * (1.0f / 256.0f));
    } else {
        g_bo[r * HDIM + j] = 0.08838834764831845f *
            cospif((float)((2 * j + 1) * (2 * r + 1)) * (1.0f / 512.0f));
    }
}

// ---------------------------------------------------------------------------
// SMEM: raw fp32 staging, rows of a 32-wide K chunk padded to 36 floats.
// ---------------------------------------------------------------------------
#define PADROW 36
#define BOFF   (128 * PADROW)
#define STAGE  (2 * 128 * PADROW)
#define SMEM_BYTES (2 * STAGE * 4)

// ---------------------------------------------------------------------------
// One 32-wide K chunk: warp tile 64x32 (4x4 m16n8 tiles), raw fp32 fragments
// split to tf32 hi/lo in registers, 3 products (AhBh + AhBl + AlBh).
// ---------------------------------------------------------------------------
__device__ __forceinline__ void compute_chunk(const float* __restrict__ buf,
                                              float acc[4][4][4],
                                              int wm, int wn, int grp, int qd) {
    const float* __restrict__ A = buf;
    const float* __restrict__ B = buf + BOFF;
    #pragma unroll
    for (int s = 0; s < 4; s++) {
        const int cc = s * 8 + qd;
        uint32_t bh[4][2], bl[4][2];
        #pragma unroll
        for (int nt = 0; nt < 4; nt++) {
            int n = wn * 32 + nt * 8 + grp;
            float v0 = B[n * PADROW + cc];
            float v1 = B[n * PADROW + cc + 4];
            float h0 = tf32f(v0), h1 = tf32f(v1);
            bh[nt][0] = __float_as_uint(h0);
            bh[nt][1] = __float_as_uint(h1);
            bl[nt][0] = __float_as_uint(tf32f(v0 - h0));
            bl[nt][1] = __float_as_uint(tf32f(v1 - h1));
        }
        #pragma unroll
        for (int mt = 0; mt < 4; mt++) {
            int r = wm * 64 + mt * 16 + grp;
            float v0 = A[r * PADROW + cc];
            float v1 = A[(r + 8) * PADROW + cc];
            float v2 = A[r * PADROW + cc + 4];
            float v3 = A[(r + 8) * PADROW + cc + 4];
            float h0 = tf32f(v0), h1 = tf32f(v1), h2 = tf32f(v2), h3 = tf32f(v3);
            uint32_t ah[4] = { __float_as_uint(h0), __float_as_uint(h1),
                               __float_as_uint(h2), __float_as_uint(h3) };
            uint32_t al[4] = { __float_as_uint(tf32f(v0 - h0)), __float_as_uint(tf32f(v1 - h1)),
                               __float_as_uint(tf32f(v2 - h2)), __float_as_uint(tf32f(v3 - h3)) };
            #pragma unroll
            for (int nt = 0; nt < 4; nt++) mma8(acc[mt][nt], ah, bh[nt]);
            #pragma unroll
            for (int nt = 0; nt < 4; nt++) mma8(acc[mt][nt], ah, bl[nt]);
            #pragma unroll
            for (int nt = 0; nt < 4; nt++) mma8(acc[mt][nt], al, bh[nt]);
        }
    }
}

// Fold prefetch: f[it][e] = src[r][col0+q*4+e] +/- src[r][255-(col0+q*4+e)]
__device__ __forceinline__ void ldg_fold(float f[4][4], const float* __restrict__ src,
                                         int col0, int r0, int q, float sgn) {
    #pragma unroll
    for (int it = 0; it < 4; it++) {
        int r = r0 + it * 32;
        float4 a = *(const float4*)(src + (size_t)r * NDIM + col0 + q * 4);
        float4 b = *(const float4*)(src + (size_t)r * NDIM + 252 - col0 - q * 4);
        f[it][0] = fmaf(sgn, b.w, a.x);
        f[it][1] = fmaf(sgn, b.z, a.y);
        f[it][2] = fmaf(sgn, b.y, a.z);
        f[it][3] = fmaf(sgn, b.x, a.w);
    }
}
__device__ __forceinline__ void sts_fold(float* __restrict__ dst, const float f[4][4],
                                         int r0, int q) {
    #pragma unroll
    for (int it = 0; it < 4; it++) {
        int r = r0 + it * 32;
        *(float4*)(dst + r * PADROW + q * 4) = make_float4(f[it][0], f[it][1], f[it][2], f[it][3]);
    }
}
// Basis staging via cp.async (HDIM-stride matrix)
__device__ __forceinline__ void stage_basis(uint32_t sb, int buf, int regionOff,
                                            const float* __restrict__ Bmat,
                                            int col0, int r0, int q) {
    #pragma unroll
    for (int it = 0; it < 4; it++) {
        int r = r0 + it * 32;
        CP16(sb + (buf * STAGE + regionOff + r * PADROW + q * 4) * 4,
             Bmat + (size_t)r * HDIM + col0 + q * 4);
    }
}

// ---------------------------------------------------------------------------
// Pass 1: Y[m, 2r+par] = sum_{j<128} fold_par(X)[m, j] * Cpar[r, j].
// Grid: 1536 CTAs, parity FASTEST-varying so the par0/par1 pair for the same
// X tile schedules adjacently -> second read hits L2.
// ---------------------------------------------------------------------------
__global__ void __launch_bounds__(256, 2) dct_p1(const float* __restrict__ X) {
    extern __shared__ float smem[];
    const uint32_t sb = smem_u32(smem);
    const int tid = threadIdx.x, lane = tid & 31, wid = tid >> 5;
    const int wm = wid >> 2, wn = wid & 3, grp = lane >> 2, qd = lane & 3;
    const int par = blockIdx.x & 1;
    const int tile = blockIdx.x >> 1;
    const int img = tile >> 1, i0 = (tile & 1) * 128;
    const float* Arow = X + (size_t)(img * NDIM + i0) * NDIM;
    const float* Bmat = par ? g_bo : g_be;
    const float sgn = par ? -1.0f : 1.0f;
    const int r0 = tid >> 3, q = tid & 7;

    float acc[4][4][4] = {};
    float fold[4][4];

    ldg_fold(fold, Arow, 0, r0, q, sgn);
    stage_basis(sb, 0, BOFF, Bmat, 0, r0, q);
    CP_COMMIT();

    for (int c = 0; c < 4; c++) {
        CP_WAIT0();
        __syncthreads();
        sts_fold(smem + (c & 1) * STAGE, fold, r0, q);
        if (c < 3) {
            ldg_fold(fold, Arow, (c + 1) * 32, r0, q, sgn);
            stage_basis(sb, (c + 1) & 1, BOFF, Bmat, (c + 1) * 32, r0, q);
            CP_COMMIT();
        }
        __syncthreads();
        compute_chunk(smem + (c & 1) * STAGE, acc, wm, wn, grp, qd);
    }
    __syncthreads();

    // Transpose through SMEM (stride 132, conflict-free), coalesced store.
    float* T = smem;
    #pragma unroll
    for (int mt = 0; mt < 4; mt++)
        #pragma unroll
        for (int nt = 0; nt < 4; nt++) {
            int m = wm * 64 + mt * 16 + grp;
            int n = wn * 32 + nt * 8 + 2 * qd;
            T[(size_t)n * 132 + m]           = acc[mt][nt][0];
            T[(size_t)(n + 1) * 132 + m]     = acc[mt][nt][1];
            T[(size_t)n * 132 + m + 8]       = acc[mt][nt][2];
            T[(size_t)(n + 1) * 132 + m + 8] = acc[mt][nt][3];
        }
    __syncthreads();

    float* dst = g_Yt + (size_t)img * NDIM * NDIM;
    #pragma unroll
    for (int rr = 0; rr < 16; rr++) {
        int n = wid * 16 + rr;
        float4 v = *(float4*)&T[(size_t)n * 132 + lane * 4];
        *(float4*)(dst + (size_t)(2 * n + par) * NDIM + i0 + lane * 4) = v;
    }
}

// ---------------------------------------------------------------------------
// Pass 2: out[img, 2r+par, k2] = f( sum_{j<128} Cpar[r, j] * fold_par(Yt)[k2, j] ).
// Parity fastest-varying (L2 pair reuse); images consumed NEWEST-FIRST so the
// L2-resident tail of Yt written by pass 1 is read before eviction.
// Output stores are streaming (evict-first).
// ---------------------------------------------------------------------------
__global__ void __launch_bounds__(256, 2) dct_p2(float* __restrict__ Out,
                                                 const float* __restrict__ meanp,
                                                 const float* __restrict__ stdp) {
    extern __shared__ float smem[];
    const uint32_t sb = smem_u32(smem);
    const int tid = threadIdx.x, lane = tid & 31, wid = tid >> 5;
    const int wm = wid >> 2, wn = wid & 3, grp = lane >> 2, qd = lane & 3;
    const int par = blockIdx.x & 1;
    const int n0 = (blockIdx.x >> 1) * 128;    // k2 tile
    const int img = NIMG - 1 - blockIdx.y;     // newest-first
    const float* Brow = g_Yt + (size_t)img * NDIM * NDIM + (size_t)n0 * NDIM;
    const float* Amat = par ? g_bo : g_be;
    const float sgn = par ? -1.0f : 1.0f;
    const int r0 = tid >> 3, q = tid & 7;

    float acc[4][4][4] = {};
    float fold[4][4];

    ldg_fold(fold, Brow, 0, r0, q, sgn);
    stage_basis(sb, 0, 0, Amat, 0, r0, q);
    CP_COMMIT();

    for (int c = 0; c < 4; c++) {
        CP_WAIT0();
        __syncthreads();
        sts_fold(smem + (c & 1) * STAGE + BOFF, fold, r0, q);
        if (c < 3) {
            ldg_fold(fold, Brow, (c + 1) * 32, r0, q, sgn);
            stage_basis(sb, (c + 1) & 1, 0, Amat, (c + 1) * 32, r0, q);
            CP_COMMIT();
        }
        __syncthreads();
        compute_chunk(smem + (c & 1) * STAGE, acc, wm, wn, grp, qd);
    }

    const float mean = *meanp;
    const float istd = 1.0f / (*stdp);
    const float sa = 0.69314718055994531f * istd;   // ln2 * istd
    const float sbias = -mean * istd;
    float* o = Out + (size_t)img * NDIM * NDIM;
    #pragma unroll
    for (int mt = 0; mt < 4; mt++)
        #pragma unroll
        for (int nt = 0; nt < 4; nt++) {
            int m = wm * 64 + mt * 16 + grp;                 // local half-row
            int n = n0 + wn * 32 + nt * 8 + 2 * qd;
            float2 v;
            v.x = fmaf(__log2f(fabsf(acc[mt][nt][0]) + EPS), sa, sbias);
            v.y = fmaf(__log2f(fabsf(acc[mt][nt][1]) + EPS), sa, sbias);
            stcs2(o + (size_t)(2 * m + par) * NDIM + n, v);
            v.x = fmaf(__log2f(fabsf(acc[mt][nt][2]) + EPS), sa, sbias);
            v.y = fmaf(__log2f(fabsf(acc[mt][nt][3]) + EPS), sa, sbias);
            stcs2(o + (size_t)(2 * (m + 8) + par) * NDIM + n, v);
        }
}

// ---------------------------------------------------------------------------
extern "C" void kernel_launch(void* const* d_in, const int* in_sizes, int n_in,
                              void* d_out, int out_size) {
    (void)in_sizes; (void)n_in; (void)out_size;
    const float* x     = (const float*)d_in[0];
    const float* meanp = (const float*)d_in[1];
    const float* stdp  = (const float*)d_in[2];
    float* out = (float*)d_out;

    cudaFuncSetAttribute(dct_p1, cudaFuncAttributeMaxDynamicSharedMemorySize, SMEM_BYTES);
    cudaFuncSetAttribute(dct_p2, cudaFuncAttributeMaxDynamicSharedMemorySize, SMEM_BYTES);

    gen_basis_kernel<<<128, 256>>>();
    dct_p1<<<dim3(1536), 256, SMEM_BYTES>>>(x);
    dct_p2<<<dim3(4, NIMG), 256, SMEM_BYTES>>>(out, meanp, stdp);
}

// round 9
// speedup vs baseline: 2.6960x; 1.0089x over previous
#include <cuda_runtime.h>
#include <math.h>
#include <cstdint>

#define NDIM 256
#define HDIM 128
#define NIMG 384
#define TOTELEM (NIMG * NDIM * NDIM)
#define EPS 1e-13f

// ---------------------------------------------------------------------------
// Static device memory. Split bases stored interleaved per 16-wide K chunk:
//   row r, chunk c occupies 32 floats: [hi(16) | lo(16)]  -> stride 256/row.
// ---------------------------------------------------------------------------
__device__ float g_Yt[TOTELEM];          // pass1 out, transposed per image
__device__ float g_beS[HDIM * 256];      // even half-basis, split-interleaved
__device__ float g_boS[HDIM * 256];      // odd  half-basis, split-interleaved

// ---------------------------------------------------------------------------
// Helpers
// ---------------------------------------------------------------------------
__device__ __forceinline__ uint32_t smem_u32(const void* p) {
    uint32_t a;
    asm("{ .reg .u64 t; cvta.to.shared.u64 t, %1; cvt.u32.u64 %0, t; }" : "=r"(a) : "l"(p));
    return a;
}
__device__ __forceinline__ float tf32f(float x) {
    uint32_t r;
    asm("cvt.rna.tf32.f32 %0, %1;" : "=r"(r) : "f"(x));
    return __uint_as_float(r);
}
// mma.sync m16n8k8 tf32: D += A*B (in-place)
__device__ __forceinline__ void mma8(float* d, const uint32_t* a, const uint32_t* b) {
    asm volatile(
        "mma.sync.aligned.m16n8k8.row.col.f32.tf32.tf32.f32 "
        "{%0,%1,%2,%3}, {%4,%5,%6,%7}, {%8,%9}, {%0,%1,%2,%3};"
        : "+f"(d[0]), "+f"(d[1]), "+f"(d[2]), "+f"(d[3])
        : "r"(a[0]), "r"(a[1]), "r"(a[2]), "r"(a[3]), "r"(b[0]), "r"(b[1]));
}
#define CP16(dst, src) asm volatile("cp.async.cg.shared.global [%0], [%1], 16;" :: "r"(dst), "l"(src))
#define CP_COMMIT()    asm volatile("cp.async.commit_group;" ::: "memory")
#define CP_WAIT0()     asm volatile("cp.async.wait_group 0;" ::: "memory")

__device__ __forceinline__ void stcs2(float* p, float2 v) {
    asm volatile("st.global.cs.v2.f32 [%0], {%1, %2};" :: "l"(p), "f"(v.x), "f"(v.y) : "memory");
}

// ---------------------------------------------------------------------------
// Half-basis generation + tf32 split into interleaved chunk layout.
// ---------------------------------------------------------------------------
__global__ void gen_basis_kernel() {
    int idx = blockIdx.x * blockDim.x + threadIdx.x;   // 0..32767
    int r = (idx >> 7) & 127, j = idx & 127;
    float v;
    if (idx < 16384) {
        float s = (r == 0) ? 0.0625f : 0.08838834764831845f;
        v = s * cospif((float)((2 * j + 1) * r) * (1.0f / 256.0f));
    } else {
        v = 0.08838834764831845f *
            cospif((float)((2 * j + 1) * (2 * r + 1)) * (1.0f / 512.0f));
    }
    float hi = tf32f(v), lo = tf32f(v - hi);
    float* dst = (idx < 16384) ? g_beS : g_boS;
    int chunk = j >> 4, pos = j & 15;
    dst[r * 256 + chunk * 32 + pos]      = hi;
    dst[r * 256 + chunk * 32 + 16 + pos] = lo;
}

// ---------------------------------------------------------------------------
// SMEM: rows of a 16-wide K chunk as [hi16 | lo16 | pad4] = 36 floats.
// Stage = A(128x36) + B(128x36) = 9216 floats; double-buffered = 73728 B.
// ---------------------------------------------------------------------------
#define PADROW 36
#define BOFF   (128 * PADROW)
#define STAGE  (2 * 128 * PADROW)
#define SMEM_BYTES (2 * STAGE * 4)
#define NCHUNK 8

// ---------------------------------------------------------------------------
// One 16-wide K chunk: warp tile 64x32, pure LDS + MMA (no split arithmetic).
// Fragment bank = (4*row + col + const) mod 32 -> conflict-free.
// ---------------------------------------------------------------------------
__device__ __forceinline__ void compute_chunk(const float* __restrict__ buf,
                                              float acc[4][4][4],
                                              int wm, int wn, int grp, int qd) {
    const float* __restrict__ A = buf;
    const float* __restrict__ B = buf + BOFF;
    #pragma unroll
    for (int s = 0; s < 2; s++) {
        const int cc = s * 8 + qd;
        uint32_t bh[4][2], bl[4][2];
        #pragma unroll
        for (int nt = 0; nt < 4; nt++) {
            int n = wn * 32 + nt * 8 + grp;
            bh[nt][0] = __float_as_uint(B[n * PADROW + cc]);
            bh[nt][1] = __float_as_uint(B[n * PADROW + cc + 4]);
            bl[nt][0] = __float_as_uint(B[n * PADROW + 16 + cc]);
            bl[nt][1] = __float_as_uint(B[n * PADROW + 16 + cc + 4]);
        }
        #pragma unroll
        for (int mt = 0; mt < 4; mt++) {
            int r = wm * 64 + mt * 16 + grp;
            uint32_t ah[4] = { __float_as_uint(A[r * PADROW + cc]),
                               __float_as_uint(A[(r + 8) * PADROW + cc]),
                               __float_as_uint(A[r * PADROW + cc + 4]),
                               __float_as_uint(A[(r + 8) * PADROW + cc + 4]) };
            uint32_t al[4] = { __float_as_uint(A[r * PADROW + 16 + cc]),
                               __float_as_uint(A[(r + 8) * PADROW + 16 + cc]),
                               __float_as_uint(A[r * PADROW + 16 + cc + 4]),
                               __float_as_uint(A[(r + 8) * PADROW + 16 + cc + 4]) };
            #pragma unroll
            for (int nt = 0; nt < 4; nt++) mma8(acc[mt][nt], ah, bh[nt]);
            #pragma unroll
            for (int nt = 0; nt < 4; nt++) mma8(acc[mt][nt], ah, bl[nt]);
            #pragma unroll
            for (int nt = 0; nt < 4; nt++) mma8(acc[mt][nt], al, bh[nt]);
        }
    }
}

// Fold prefetch (16-wide chunk): r = (tid>>2)+it*64, q = tid&3.
// f[it] = src[r][c*16+q*4 .. +3] +/- src[r][255-(c*16+q*4) .. -3]
__device__ __forceinline__ void ldg_fold(float f[2][4], const float* __restrict__ src,
                                         int c, int tid, float sgn) {
    const int q = tid & 3;
    #pragma unroll
    for (int it = 0; it < 2; it++) {
        int r = (tid >> 2) + it * 64;
        float4 a = *(const float4*)(src + (size_t)r * NDIM + c * 16 + q * 4);
        float4 b = *(const float4*)(src + (size_t)r * NDIM + 252 - c * 16 - q * 4);
        f[it][0] = fmaf(sgn, b.w, a.x);
        f[it][1] = fmaf(sgn, b.z, a.y);
        f[it][2] = fmaf(sgn, b.y, a.z);
        f[it][3] = fmaf(sgn, b.x, a.w);
    }
}
// Split once and store interleaved hi/lo.
__device__ __forceinline__ void sts_fold(float* __restrict__ dst, const float f[2][4],
                                         int tid) {
    const int q = tid & 3;
    #pragma unroll
    for (int it = 0; it < 2; it++) {
        int r = (tid >> 2) + it * 64;
        float h0 = tf32f(f[it][0]), h1 = tf32f(f[it][1]);
        float h2 = tf32f(f[it][2]), h3 = tf32f(f[it][3]);
        *(float4*)(dst + r * PADROW + q * 4) = make_float4(h0, h1, h2, h3);
        *(float4*)(dst + r * PADROW + 16 + q * 4) =
            make_float4(tf32f(f[it][0] - h0), tf32f(f[it][1] - h1),
                        tf32f(f[it][2] - h2), tf32f(f[it][3] - h3));
    }
}
// Split-basis staging via cp.async: 32 floats (hi16|lo16) per row per chunk.
__device__ __forceinline__ void stage_basis(uint32_t sb, int buf, int regionOff,
                                            const float* __restrict__ Bmat,
                                            int c, int tid) {
    const int r0 = tid >> 3, q = tid & 7;
    #pragma unroll
    for (int it = 0; it < 4; it++) {
        int r = r0 + it * 32;
        CP16(sb + (buf * STAGE + regionOff + r * PADROW + q * 4) * 4,
             Bmat + (size_t)r * 256 + c * 32 + q * 4);
    }
}

// ---------------------------------------------------------------------------
// Pass 1: Y[m, 2r+par] = sum_{j<128} fold_par(X)[m, j] * Cpar[r, j].
// Parity fastest-varying (L2 pair reuse on X tiles).
// ---------------------------------------------------------------------------
__global__ void __launch_bounds__(256, 2) dct_p1(const float* __restrict__ X) {
    extern __shared__ float smem[];
    const uint32_t sb = smem_u32(smem);
    const int tid = threadIdx.x, lane = tid & 31, wid = tid >> 5;
    const int wm = wid >> 2, wn = wid & 3, grp = lane >> 2, qd = lane & 3;
    const int par = blockIdx.x & 1;
    const int tile = blockIdx.x >> 1;
    const int img = tile >> 1, i0 = (tile & 1) * 128;
    const float* Arow = X + (size_t)(img * NDIM + i0) * NDIM;
    const float* Bmat = par ? g_boS : g_beS;
    const float sgn = par ? -1.0f : 1.0f;

    float acc[4][4][4] = {};
    float fold[2][4];

    ldg_fold(fold, Arow, 0, tid, sgn);
    stage_basis(sb, 0, BOFF, Bmat, 0, tid);
    CP_COMMIT();

    for (int c = 0; c < NCHUNK; c++) {
        CP_WAIT0();
        __syncthreads();
        sts_fold(smem + (c & 1) * STAGE, fold, tid);
        if (c < NCHUNK - 1) {
            ldg_fold(fold, Arow, c + 1, tid, sgn);
            stage_basis(sb, (c + 1) & 1, BOFF, Bmat, c + 1, tid);
            CP_COMMIT();
        }
        __syncthreads();
        compute_chunk(smem + (c & 1) * STAGE, acc, wm, wn, grp, qd);
    }
    __syncthreads();

    // Transpose through SMEM (stride 132, conflict-free), coalesced store.
    float* T = smem;
    #pragma unroll
    for (int mt = 0; mt < 4; mt++)
        #pragma unroll
        for (int nt = 0; nt < 4; nt++) {
            int m = wm * 64 + mt * 16 + grp;
            int n = wn * 32 + nt * 8 + 2 * qd;
            T[(size_t)n * 132 + m]           = acc[mt][nt][0];
            T[(size_t)(n + 1) * 132 + m]     = acc[mt][nt][1];
            T[(size_t)n * 132 + m + 8]       = acc[mt][nt][2];
            T[(size_t)(n + 1) * 132 + m + 8] = acc[mt][nt][3];
        }
    __syncthreads();

    float* dst = g_Yt + (size_t)img * NDIM * NDIM;
    #pragma unroll
    for (int rr = 0; rr < 16; rr++) {
        int n = wid * 16 + rr;
        float4 v = *(float4*)&T[(size_t)n * 132 + lane * 4];
        *(float4*)(dst + (size_t)(2 * n + par) * NDIM + i0 + lane * 4) = v;
    }
}

// ---------------------------------------------------------------------------
// Pass 2: out[img, 2r+par, k2] = f( sum_{j<128} Cpar[r, j] * fold_par(Yt)[k2, j] ).
// Images newest-first; streaming output stores.
// ---------------------------------------------------------------------------
__global__ void __launch_bounds__(256, 2) dct_p2(float* __restrict__ Out,
                                                 const float* __restrict__ meanp,
                                                 const float* __restrict__ stdp) {
    extern __shared__ float smem[];
    const uint32_t sb = smem_u32(smem);
    const int tid = threadIdx.x, lane = tid & 31, wid = tid >> 5;
    const int wm = wid >> 2, wn = wid & 3, grp = lane >> 2, qd = lane & 3;
    const int par = blockIdx.x & 1;
    const int n0 = (blockIdx.x >> 1) * 128;    // k2 tile
    const int img = NIMG - 1 - blockIdx.y;     // newest-first
    const float* Brow = g_Yt + (size_t)img * NDIM * NDIM + (size_t)n0 * NDIM;
    const float* Amat = par ? g_boS : g_beS;
    const float sgn = par ? -1.0f : 1.0f;

    float acc[4][4][4] = {};
    float fold[2][4];

    ldg_fold(fold, Brow, 0, tid, sgn);
    stage_basis(sb, 0, 0, Amat, 0, tid);
    CP_COMMIT();

    for (int c = 0; c < NCHUNK; c++) {
        CP_WAIT0();
        __syncthreads();
        sts_fold(smem + (c & 1) * STAGE + BOFF, fold, tid);
        if (c < NCHUNK - 1) {
            ldg_fold(fold, Brow, c + 1, tid, sgn);
            stage_basis(sb, (c + 1) & 1, 0, Amat, c + 1, tid);
            CP_COMMIT();
        }
        __syncthreads();
        compute_chunk(smem + (c & 1) * STAGE, acc, wm, wn, grp, qd);
    }

    const float mean = *meanp;
    const float istd = 1.0f / (*stdp);
    const float sa = 0.69314718055994531f * istd;   // ln2 * istd
    const float sbias = -mean * istd;
    float* o = Out + (size_t)img * NDIM * NDIM;
    #pragma unroll
    for (int mt = 0; mt < 4; mt++)
        #pragma unroll
        for (int nt = 0; nt < 4; nt++) {
            int m = wm * 64 + mt * 16 + grp;                 // local half-row
            int n = n0 + wn * 32 + nt * 8 + 2 * qd;
            float2 v;
            v.x = fmaf(__log2f(fabsf(acc[mt][nt][0]) + EPS), sa, sbias);
            v.y = fmaf(__log2f(fabsf(acc[mt][nt][1]) + EPS), sa, sbias);
            stcs2(o + (size_t)(2 * m + par) * NDIM + n, v);
            v.x = fmaf(__log2f(fabsf(acc[mt][nt][2]) + EPS), sa, sbias);
            v.y = fmaf(__log2f(fabsf(acc[mt][nt][3]) + EPS), sa, sbias);
            stcs2(o + (size_t)(2 * (m + 8) + par) * NDIM + n, v);
        }
}

// ---------------------------------------------------------------------------
extern "C" void kernel_launch(void* const* d_in, const int* in_sizes, int n_in,
                              void* d_out, int out_size) {
    (void)in_sizes; (void)n_in; (void)out_size;
    const float* x     = (const float*)d_in[0];
    const float* meanp = (const float*)d_in[1];
    const float* stdp  = (const float*)d_in[2];
    float* out = (float*)d_out;

    cudaFuncSetAttribute(dct_p1, cudaFuncAttributeMaxDynamicSharedMemorySize, SMEM_BYTES);
    cudaFuncSetAttribute(dct_p2, cudaFuncAttributeMaxDynamicSharedMemorySize, SMEM_BYTES);

    gen_basis_kernel<<<128, 256>>>();
    dct_p1<<<dim3(1536), 256, SMEM_BYTES>>>(x);
    dct_p2<<<dim3(4, NIMG), 256, SMEM_BYTES>>>(out, meanp, stdp);
}

// round 11
// speedup vs baseline: 4.3655x; 1.6192x over previous
#include <cuda_runtime.h>
#include <cuda_fp16.h>
#include <math.h>
#include <cstring>
#include <cstdint>

#define NDIM 256
#define HDIM 128
#define NIMG 384
#define TOTELEM (NIMG * NDIM * NDIM)
#define EPS 1e-13f

// ---------------------------------------------------------------------------
// Static device memory. Split fp16 bases stored per 32-wide K chunk:
//   [r][chunk][hi32 | lo32]  -> 256 halves per row.
// ---------------------------------------------------------------------------
__device__ float g_Yt[TOTELEM];            // pass1 out, transposed per image
__device__ __half g_beS[HDIM * 256];       // even half-basis, split fp16
__device__ __half g_boS[HDIM * 256];       // odd  half-basis, split fp16

// ---------------------------------------------------------------------------
// Helpers
// ---------------------------------------------------------------------------
__device__ __forceinline__ uint32_t smem_u32(const void* p) {
    uint32_t a;
    asm("{ .reg .u64 t; cvta.to.shared.u64 t, %1; cvt.u32.u64 %0, t; }" : "=r"(a) : "l"(p));
    return a;
}
__device__ __forceinline__ uint32_t h2_u32(__half2 h) {
    uint32_t u;
    memcpy(&u, &h, 4);
    return u;
}
// mma.sync m16n8k16 fp16 -> fp32: D += A*B (in-place)
__device__ __forceinline__ void mma16(float* d, const uint32_t* a, const uint32_t* b) {
    asm volatile(
        "mma.sync.aligned.m16n8k16.row.col.f32.f16.f16.f32 "
        "{%0,%1,%2,%3}, {%4,%5,%6,%7}, {%8,%9}, {%0,%1,%2,%3};"
        : "+f"(d[0]), "+f"(d[1]), "+f"(d[2]), "+f"(d[3])
        : "r"(a[0]), "r"(a[1]), "r"(a[2]), "r"(a[3]), "r"(b[0]), "r"(b[1]));
}
#define CP16(dst, src) asm volatile("cp.async.cg.shared.global [%0], [%1], 16;" :: "r"(dst), "l"(src))
#define CP_COMMIT()    asm volatile("cp.async.commit_group;" ::: "memory")
#define CP_WAIT0()     asm volatile("cp.async.wait_group 0;" ::: "memory")

__device__ __forceinline__ void stcs2(float* p, float2 v) {
    asm volatile("st.global.cs.v2.f32 [%0], {%1, %2};" :: "l"(p), "f"(v.x), "f"(v.y) : "memory");
}

// ---------------------------------------------------------------------------
// Half-basis generation + fp16 split into chunked [hi32|lo32] layout.
//   Ce[r][j] = s_{2r}  * cos(pi*(2j+1)*r/256)
//   Co[r][j] = sqrt(2/256) * cos(pi*(2j+1)*(2r+1)/512)
// ---------------------------------------------------------------------------
__global__ void gen_basis_kernel() {
    int idx = blockIdx.x * blockDim.x + threadIdx.x;   // 0..32767
    int r = (idx >> 7) & 127, j = idx & 127;
    float v;
    if (idx < 16384) {
        float s = (r == 0) ? 0.0625f : 0.08838834764831845f;
        v = s * cospif((float)((2 * j + 1) * r) * (1.0f / 256.0f));
    } else {
        v = 0.08838834764831845f *
            cospif((float)((2 * j + 1) * (2 * r + 1)) * (1.0f / 512.0f));
    }
    __half hi = __float2half_rn(v);
    __half lo = __float2half_rn(v - __half2float(hi));
    __half* dst = (idx < 16384) ? g_beS : g_boS;
    int chunk = j >> 5, pos = j & 31;
    dst[r * 256 + chunk * 64 + pos]      = hi;
    dst[r * 256 + chunk * 64 + 32 + pos] = lo;
}

// ---------------------------------------------------------------------------
// SMEM (in 4-byte words): row of a 32-wide K chunk = [hi32 f16 | lo32 f16 | pad]
// = 36 words (144 B). 36 mod 32 = 4 -> fragment LDS conflict-free.
// Stage = A(128x36) + B(128x36) = 9216 words; double-buffered = 73728 B.
// ---------------------------------------------------------------------------
#define PADW  36
#define BOFFW (128 * PADW)       // 4608 words
#define STAGEW (2 * 128 * PADW)  // 9216 words
#define SMEM_BYTES (2 * STAGEW * 4)
#define NCHUNK 4                 // K = 128 in chunks of 32

// ---------------------------------------------------------------------------
// One 32-wide K chunk: warp tile 64x32, 2 k16 steps, pure LDS + MMA.
// ---------------------------------------------------------------------------
__device__ __forceinline__ void compute_chunk(const uint32_t* __restrict__ buf,
                                              float acc[4][4][4],
                                              int wm, int wn, int grp, int qd) {
    const uint32_t* __restrict__ A = buf;
    const uint32_t* __restrict__ B = buf + BOFFW;
    #pragma unroll
    for (int s = 0; s < 2; s++) {
        const int base = s * 8 + qd;
        uint32_t bh[4][2], bl[4][2];
        #pragma unroll
        for (int nt = 0; nt < 4; nt++) {
            int n = wn * 32 + nt * 8 + grp;
            bh[nt][0] = B[n * PADW + base];
            bh[nt][1] = B[n * PADW + base + 4];
            bl[nt][0] = B[n * PADW + 16 + base];
            bl[nt][1] = B[n * PADW + 16 + base + 4];
        }
        #pragma unroll
        for (int mt = 0; mt < 4; mt++) {
            int r = wm * 64 + mt * 16 + grp;
            uint32_t ah[4] = { A[r * PADW + base],      A[(r + 8) * PADW + base],
                               A[r * PADW + base + 4],  A[(r + 8) * PADW + base + 4] };
            uint32_t al[4] = { A[r * PADW + 16 + base],     A[(r + 8) * PADW + 16 + base],
                               A[r * PADW + 16 + base + 4], A[(r + 8) * PADW + 16 + base + 4] };
            #pragma unroll
            for (int nt = 0; nt < 4; nt++) mma16(acc[mt][nt], ah, bh[nt]);
            #pragma unroll
            for (int nt = 0; nt < 4; nt++) mma16(acc[mt][nt], ah, bl[nt]);
            #pragma unroll
            for (int nt = 0; nt < 4; nt++) mma16(acc[mt][nt], al, bh[nt]);
        }
    }
}

// Fold prefetch: thread handles 8 consecutive k per row, 2 rows.
// f[it][e] = src[r][j0+e] + sgn*src[r][255-j0-e], j0 = c*32 + q*8.
__device__ __forceinline__ void ldg_fold(float f[2][8], const float* __restrict__ src,
                                         int c, int tid, float sgn) {
    const int q = tid & 3;
    const int j0 = c * 32 + q * 8;
    #pragma unroll
    for (int it = 0; it < 2; it++) {
        int r = (tid >> 2) + it * 64;
        const float* row = src + (size_t)r * NDIM;
        float4 a0 = *(const float4*)(row + j0);
        float4 a1 = *(const float4*)(row + j0 + 4);
        float4 m0 = *(const float4*)(row + 252 - j0);
        float4 m1 = *(const float4*)(row + 248 - j0);
        f[it][0] = fmaf(sgn, m0.w, a0.x);
        f[it][1] = fmaf(sgn, m0.z, a0.y);
        f[it][2] = fmaf(sgn, m0.y, a0.z);
        f[it][3] = fmaf(sgn, m0.x, a0.w);
        f[it][4] = fmaf(sgn, m1.w, a1.x);
        f[it][5] = fmaf(sgn, m1.z, a1.y);
        f[it][6] = fmaf(sgn, m1.y, a1.z);
        f[it][7] = fmaf(sgn, m1.x, a1.w);
    }
}
// Split once to fp16 hi/lo and store 16B each.
__device__ __forceinline__ void sts_fold(float* __restrict__ smemf, int wordBase,
                                         const float f[2][8], int tid) {
    const int q = tid & 3;
    #pragma unroll
    for (int it = 0; it < 2; it++) {
        int r = (tid >> 2) + it * 64;
        __half h[8];
        float l[8];
        #pragma unroll
        for (int e = 0; e < 8; e++) {
            h[e] = __float2half_rn(f[it][e]);
            l[e] = f[it][e] - __half2float(h[e]);
        }
        uint4 hv, lv;
        hv.x = h2_u32(__halves2half2(h[0], h[1]));
        hv.y = h2_u32(__halves2half2(h[2], h[3]));
        hv.z = h2_u32(__halves2half2(h[4], h[5]));
        hv.w = h2_u32(__halves2half2(h[6], h[7]));
        lv.x = h2_u32(__floats2half2_rn(l[0], l[1]));
        lv.y = h2_u32(__floats2half2_rn(l[2], l[3]));
        lv.z = h2_u32(__floats2half2_rn(l[4], l[5]));
        lv.w = h2_u32(__floats2half2_rn(l[6], l[7]));
        *(uint4*)(smemf + wordBase + r * PADW + q * 4)      = hv;
        *(uint4*)(smemf + wordBase + r * PADW + 16 + q * 4) = lv;
    }
}
// Split-basis staging via cp.async: 128B (hi32|lo32) per row per chunk.
__device__ __forceinline__ void stage_basis(uint32_t sb, int buf, int regionOff,
                                            const __half* __restrict__ Bmat,
                                            int c, int tid) {
    const int r0 = tid >> 3, q8 = tid & 7;
    #pragma unroll
    for (int it = 0; it < 4; it++) {
        int r = r0 + it * 32;
        CP16(sb + (buf * STAGEW + regionOff + r * PADW + q8 * 4) * 4,
             Bmat + (size_t)r * 256 + c * 64 + q8 * 8);
    }
}

// ---------------------------------------------------------------------------
// Pass 1: Y[m, 2r+par] = sum_{j<128} fold_par(X)[m, j] * Cpar[r, j].
// ---------------------------------------------------------------------------
__global__ void __launch_bounds__(256, 2) dct_p1(const float* __restrict__ X) {
    extern __shared__ float smem[];
    const uint32_t sb = smem_u32(smem);
    const int tid = threadIdx.x, lane = tid & 31, wid = tid >> 5;
    const int wm = wid >> 2, wn = wid & 3, grp = lane >> 2, qd = lane & 3;
    const int par = blockIdx.x & 1;
    const int tile = blockIdx.x >> 1;
    const int img = tile >> 1, i0 = (tile & 1) * 128;
    const float* Arow = X + (size_t)(img * NDIM + i0) * NDIM;
    const __half* Bmat = par ? g_boS : g_beS;
    const float sgn = par ? -1.0f : 1.0f;

    float acc[4][4][4] = {};
    float fold[2][8];

    ldg_fold(fold, Arow, 0, tid, sgn);
    stage_basis(sb, 0, BOFFW, Bmat, 0, tid);
    CP_COMMIT();

    for (int c = 0; c < NCHUNK; c++) {
        CP_WAIT0();
        __syncthreads();
        sts_fold(smem, (c & 1) * STAGEW, fold, tid);
        if (c < NCHUNK - 1) {
            ldg_fold(fold, Arow, c + 1, tid, sgn);
            stage_basis(sb, (c + 1) & 1, BOFFW, Bmat, c + 1, tid);
            CP_COMMIT();
        }
        __syncthreads();
        compute_chunk((const uint32_t*)smem + (c & 1) * STAGEW, acc, wm, wn, grp, qd);
    }
    __syncthreads();

    // Transpose through SMEM (stride 132, conflict-free), coalesced store.
    float* T = smem;
    #pragma unroll
    for (int mt = 0; mt < 4; mt++)
        #pragma unroll
        for (int nt = 0; nt < 4; nt++) {
            int m = wm * 64 + mt * 16 + grp;
            int n = wn * 32 + nt * 8 + 2 * qd;
            T[(size_t)n * 132 + m]           = acc[mt][nt][0];
            T[(size_t)(n + 1) * 132 + m]     = acc[mt][nt][1];
            T[(size_t)n * 132 + m + 8]       = acc[mt][nt][2];
            T[(size_t)(n + 1) * 132 + m + 8] = acc[mt][nt][3];
        }
    __syncthreads();

    float* dst = g_Yt + (size_t)img * NDIM * NDIM;
    #pragma unroll
    for (int rr = 0; rr < 16; rr++) {
        int n = wid * 16 + rr;
        float4 v = *(float4*)&T[(size_t)n * 132 + lane * 4];
        *(float4*)(dst + (size_t)(2 * n + par) * NDIM + i0 + lane * 4) = v;
    }
}

// ---------------------------------------------------------------------------
// Pass 2: out[img, 2r+par, k2] = f( sum_{j<128} Cpar[r, j] * fold_par(Yt)[k2, j] ).
// ---------------------------------------------------------------------------
__global__ void __launch_bounds__(256, 2) dct_p2(float* __restrict__ Out,
                                                 const float* __restrict__ meanp,
                                                 const float* __restrict__ stdp) {
    extern __shared__ float smem[];
    const uint32_t sb = smem_u32(smem);
    const int tid = threadIdx.x, lane = tid & 31, wid = tid >> 5;
    const int wm = wid >> 2, wn = wid & 3, grp = lane >> 2, qd = lane & 3;
    const int par = blockIdx.x & 1;
    const int n0 = (blockIdx.x >> 1) * 128;    // k2 tile
    const int img = NIMG - 1 - blockIdx.y;     // newest-first
    const float* Brow = g_Yt + (size_t)img * NDIM * NDIM + (size_t)n0 * NDIM;
    const __half* Amat = par ? g_boS : g_beS;
    const float sgn = par ? -1.0f : 1.0f;

    float acc[4][4][4] = {};
    float fold[2][8];

    ldg_fold(fold, Brow, 0, tid, sgn);
    stage_basis(sb, 0, 0, Amat, 0, tid);
    CP_COMMIT();

    for (int c = 0; c < NCHUNK; c++) {
        CP_WAIT0();
        __syncthreads();
        sts_fold(smem, (c & 1) * STAGEW + BOFFW, fold, tid);
        if (c < NCHUNK - 1) {
            ldg_fold(fold, Brow, c + 1, tid, sgn);
            stage_basis(sb, (c + 1) & 1, 0, Amat, c + 1, tid);
            CP_COMMIT();
        }
        __syncthreads();
        compute_chunk((const uint32_t*)smem + (c & 1) * STAGEW, acc, wm, wn, grp, qd);
    }

    const float mean = *meanp;
    const float istd = 1.0f / (*stdp);
    const float sa = 0.69314718055994531f * istd;   // ln2 * istd
    const float sbias = -mean * istd;
    float* o = Out + (size_t)img * NDIM * NDIM;
    #pragma unroll
    for (int mt = 0; mt < 4; mt++)
        #pragma unroll
        for (int nt = 0; nt < 4; nt++) {
            int m = wm * 64 + mt * 16 + grp;                 // local half-row
            int n = n0 + wn * 32 + nt * 8 + 2 * qd;
            float2 v;
            v.x = fmaf(__log2f(fabsf(acc[mt][nt][0]) + EPS), sa, sbias);
            v.y = fmaf(__log2f(fabsf(acc[mt][nt][1]) + EPS), sa, sbias);
            stcs2(o + (size_t)(2 * m + par) * NDIM + n, v);
            v.x = fmaf(__log2f(fabsf(acc[mt][nt][2]) + EPS), sa, sbias);
            v.y = fmaf(__log2f(fabsf(acc[mt][nt][3]) + EPS), sa, sbias);
            stcs2(o + (size_t)(2 * (m + 8) + par) * NDIM + n, v);
        }
}

// ---------------------------------------------------------------------------
extern "C" void kernel_launch(void* const* d_in, const int* in_sizes, int n_in,
                              void* d_out, int out_size) {
    (void)in_sizes; (void)n_in; (void)out_size;
    const float* x     = (const float*)d_in[0];
    const float* meanp = (const float*)d_in[1];
    const float* stdp  = (const float*)d_in[2];
    float* out = (float*)d_out;

    cudaFuncSetAttribute(dct_p1, cudaFuncAttributeMaxDynamicSharedMemorySize, SMEM_BYTES);
    cudaFuncSetAttribute(dct_p2, cudaFuncAttributeMaxDynamicSharedMemorySize, SMEM_BYTES);

    gen_basis_kernel<<<128, 256>>>();
    dct_p1<<<dim3(1536), 256, SMEM_BYTES>>>(x);
    dct_p2<<<dim3(4, NIMG), 256, SMEM_BYTES>>>(out, meanp, stdp);
}